// round 7
// baseline (speedup 1.0000x reference)
#include <cuda_runtime.h>
#include <math.h>

#define BATCH 64
#define CH    64
#define NPT   256

typedef unsigned long long u64;

// ---------------- global scratch ----------------
// g_proj rows per batch: 0-7 ga_q, 8-15 ga_k, 16-47 ga_v(raw), 48-55 sa_q,
// 56-63 sa_k, 64-95 sa_v(raw), 96-127 ga_lb, 128-159 sa_lb   (layout [row][n])
__device__ float g_proj[BATCH * 160 * NPT];
__device__ float g_f[BATCH * NPT * CH];     // TRANSPOSED: [b][n][ch]
__device__ float g_h[BATCH * NPT * 256];    // TRANSPOSED: [b][n][o]

// ---------------- f32x2 helpers ----------------
__device__ __forceinline__ u64 f2pack(float a, float b) {
    u64 r;
    asm("mov.b64 %0, {%1, %2};" : "=l"(r) : "r"(__float_as_uint(a)), "r"(__float_as_uint(b)));
    return r;
}
__device__ __forceinline__ u64 ffma2(u64 a, u64 b, u64 c) {
    u64 d;
    asm("fma.rn.f32x2 %0, %1, %2, %3;" : "=l"(d) : "l"(a), "l"(b), "l"(c));
    return d;
}
__device__ __forceinline__ u64 fadd2(u64 a, u64 b) {
    u64 d;
    asm("add.rn.f32x2 %0, %1, %2;" : "=l"(d) : "l"(a), "l"(b));
    return d;
}
__device__ __forceinline__ void unpack2(u64 v, float& lo, float& hi) {
    unsigned int l, h;
    asm("mov.b64 {%0, %1}, %2;" : "=r"(l), "=r"(h) : "l"(v));
    lo = __uint_as_float(l);
    hi = __uint_as_float(h);
}
__device__ __forceinline__ float hsum2(u64 v) {
    float lo, hi;
    unpack2(v, lo, hi);
    return lo + hi;
}
__device__ __forceinline__ void bn_coef(const float* __restrict__ p, int ch, int cn,
                                        float& sc, float& sh) {
    float ga = __ldg(p + ch);
    float be = __ldg(p + cn + ch);
    float mu = __ldg(p + 2 * cn + ch);
    float va = __ldg(p + 3 * cn + ch);
    sc = ga * rsqrtf(va + 1e-5f);
    sh = fmaf(-mu, sc, be);
}

// ---------------- kernel 1: projections ----------------
// grid (64, 16): y>>1 = out group (20 rows), y&1 = n half. block 128.
__global__ void proj_kernel(const float* __restrict__ x,
                            const float* __restrict__ ga_q_w, const float* __restrict__ ga_k_w,
                            const float* __restrict__ ga_v_w, const float* __restrict__ ga_lb_w,
                            const float* __restrict__ sa_q_w, const float* __restrict__ sa_k_w,
                            const float* __restrict__ sa_v_w, const float* __restrict__ sa_lb_w) {
    __shared__ float ws[20 * 64];
    int b = blockIdx.x, tid = threadIdx.x;
    int og = blockIdx.y >> 1, nh = blockIdx.y & 1;
    int n = nh * 128 + tid;

    for (int i = tid; i < 1280; i += 128) {
        int r = og * 20 + (i >> 6), c = i & 63;
        float v;
        if      (r < 8)   v = __ldg(&ga_q_w[r * 64 + c]);
        else if (r < 16)  v = __ldg(&ga_k_w[(r - 8) * 64 + c]);
        else if (r < 48)  v = __ldg(&ga_v_w[(r - 16) * 64 + c]);
        else if (r < 56)  v = __ldg(&sa_q_w[(r - 48) * 64 + c]);
        else if (r < 64)  v = __ldg(&sa_k_w[(r - 56) * 64 + c]);
        else if (r < 96)  v = __ldg(&sa_v_w[(r - 64) * 64 + c]);
        else if (r < 128) v = __ldg(&ga_lb_w[(r - 96) * 64 + c]);
        else              v = __ldg(&sa_lb_w[(r - 128) * 64 + c]);
        ws[i] = v;
    }
    __syncthreads();

    u64 xr2[32];
#pragma unroll
    for (int c = 0; c < 32; c++) {
        float a = __ldg(&x[b * 16384 + (2 * c) * 256 + n]);
        float bb = __ldg(&x[b * 16384 + (2 * c + 1) * 256 + n]);
        xr2[c] = f2pack(a, bb);
    }

    float* outp = g_proj + (b * 160 + og * 20) * 256 + n;
#pragma unroll 2
    for (int o = 0; o < 20; o++) {
        const ulonglong2* w2 = (const ulonglong2*)(ws + o * 64);
        u64 a0 = 0ULL, a1 = 0ULL;
#pragma unroll
        for (int i = 0; i < 16; i++) {
            ulonglong2 wv = w2[i];
            a0 = ffma2(wv.x, xr2[2 * i], a0);
            a1 = ffma2(wv.y, xr2[2 * i + 1], a1);
        }
        outp[o * 256] = hsum2(fadd2(a0, a1));
    }
}

// ---------------- kernel 2: attention ----------------
// grid (64, 8): by>>2 = branch, by&3 = row chunk (64 rows).
// block 256 = 64 rows x 4 m-quarters. Warp-uniform m => broadcast LDS.
#define KS_OFF  0
#define VS_OFF  2048
#define MB_OFF  11264      // 6144-float union: SA bins (16x256) / V-merge (64x48 u64)
#define MX_OFF  17408
#define EB_OFF  17664
#define STK_OFF 17920
#define ATTN_SMEM_BYTES (18176 * 4)

__global__ void attn_kernel(const int* __restrict__ stroke_idx,
                            const float* __restrict__ ga_v_b, const float* __restrict__ sa_v_b,
                            const float* __restrict__ ga_bn_p, const float* __restrict__ ga_lb_bn_p,
                            const float* __restrict__ sa_bn_p, const float* __restrict__ sa_lb_bn_p) {
    extern __shared__ float sm[];
    float* Ks  = sm + KS_OFF;     // [m*8 + j]
    float* Vs  = sm + VS_OFF;     // [m*36 + o]
    float* MB  = sm + MB_OFF;     // bins / V-merge
    float* MX  = sm + MX_OFF;
    float* EB  = sm + EB_OFF;
    int*   stk = (int*)(sm + STK_OFF);

    int b = blockIdx.x, tid = threadIdx.x;
    int branch = blockIdx.y >> 2, rc = blockIdx.y & 3;
    int row = tid & 63, mh = tid >> 6;
    int n = rc * 64 + row;
    int m0 = mh * 64;

    int qbase  = branch ? 48 : 0;
    int kbase  = qbase + 8;
    int vbase  = branch ? 64 : 16;
    int lbbase = branch ? 128 : 96;
    int choff  = branch ? 32 : 0;
    const float* vb = branch ? sa_v_b : ga_v_b;
    const float* gp = g_proj + b * 160 * 256;
    const float* bnp  = branch ? sa_bn_p : ga_bn_p;
    const float* bnlb = branch ? sa_lb_bn_p : ga_lb_bn_p;

    for (int i = tid; i < 2048; i += 256) {
        int r = i >> 8, m = i & 255;
        Ks[m * 8 + r] = gp[(kbase + r) * 256 + m];
    }
    for (int i = tid; i < 8192; i += 256) {
        int r = i >> 8, m = i & 255;
        Vs[m * 36 + r] = gp[(vbase + r) * 256 + m] + __ldg(vb + r);
    }
    if (branch)
        for (int i = tid; i < 256; i += 256) stk[i] = stroke_idx[b * 256 + i];
    __syncthreads();

    u64 q2[4];
#pragma unroll
    for (int j = 0; j < 4; j++)
        q2[j] = f2pack(gp[(qbase + 2 * j) * 256 + n], gp[(qbase + 2 * j + 1) * 256 + n]);

    const float INV_GA = 0.35355339059327373f;   // 1/sqrt(8)
    const float ESC    = 3.5355339059327378f;    // 10/sqrt(8)

    // ---- max over own quarter, merge 4 ----
    float mxl = -1e30f;
#pragma unroll 4
    for (int m = m0; m < m0 + 64; m++) {
        const ulonglong2* k2 = (const ulonglong2*)(Ks + m * 8);
        ulonglong2 ka = k2[0], kb = k2[1];
        u64 d0 = ffma2(q2[0], ka.x, 0ULL);
        d0 = ffma2(q2[1], ka.y, d0);
        d0 = ffma2(q2[2], kb.x, d0);
        d0 = ffma2(q2[3], kb.y, d0);
        mxl = fmaxf(mxl, hsum2(d0));
    }
    MX[tid] = mxl;
    __syncthreads();
    float mx = fmaxf(fmaxf(MX[row], MX[row + 64]), fmaxf(MX[row + 128], MX[row + 192]));

    u64 o2[16];
#pragma unroll
    for (int v = 0; v < 16; v++) o2[v] = 0ULL;
    u64* vm = (u64*)MB;    // merge area: [row*48 + (mh-1)*16 + j]

    if (branch == 0) {
        // ---- GA ----
        float sum = 0.f;
#pragma unroll 2
        for (int m = m0; m < m0 + 64; m++) {
            const ulonglong2* k2 = (const ulonglong2*)(Ks + m * 8);
            ulonglong2 ka = k2[0], kb = k2[1];
            u64 d0 = ffma2(q2[0], ka.x, 0ULL);
            d0 = ffma2(q2[1], ka.y, d0);
            d0 = ffma2(q2[2], kb.x, d0);
            d0 = ffma2(q2[3], kb.y, d0);
            float e = __expf((hsum2(d0) - mx) * INV_GA);
            sum += e;
            u64 ep = f2pack(e, e);
            const ulonglong2* v2p = (const ulonglong2*)(Vs + m * 36);
#pragma unroll
            for (int g = 0; g < 8; g++) {
                ulonglong2 vv = v2p[g];
                o2[2 * g]     = ffma2(ep, vv.x, o2[2 * g]);
                o2[2 * g + 1] = ffma2(ep, vv.y, o2[2 * g + 1]);
            }
        }
        EB[tid] = sum;
        if (mh != 0) {
#pragma unroll
            for (int j = 0; j < 16; j++) vm[row * 48 + (mh - 1) * 16 + j] = o2[j];
        }
        __syncthreads();
        if (mh == 0) {
            float sumt = EB[row] + EB[row + 64] + EB[row + 128] + EB[row + 192];
            float rcp = 1.f / sumt;
            float vals[32];
#pragma unroll
            for (int g = 0; g < 16; g++) {
                o2[g] = fadd2(fadd2(o2[g], vm[row * 48 + g]),
                              fadd2(vm[row * 48 + 16 + g], vm[row * 48 + 32 + g]));
                float v0, v1;
                unpack2(o2[g], v0, v1);
                int c0 = 2 * g;
                float sc1, sh1, sc2, sh2;
                bn_coef(bnp, c0, 32, sc1, sh1);
                bn_coef(bnlb, c0, 32, sc2, sh2);
                float lb0 = gp[(lbbase + c0) * 256 + n];
                vals[c0] = fmaf(v0 * rcp, sc1, sh1) + fmaf(lb0, sc2, sh2);
                bn_coef(bnp, c0 + 1, 32, sc1, sh1);
                bn_coef(bnlb, c0 + 1, 32, sc2, sh2);
                float lb1 = gp[(lbbase + c0 + 1) * 256 + n];
                vals[c0 + 1] = fmaf(v1 * rcp, sc1, sh1) + fmaf(lb1, sc2, sh2);
            }
            float* fout = g_f + b * 16384 + n * 64 + choff;
#pragma unroll
            for (int q = 0; q < 8; q++)
                *(float4*)(fout + 4 * q) = *(float4*)(vals + 4 * q);
        }
    } else {
        // ---- SA: collapsed 16-stroke masked softmax sum ----
        const float CC  = 1.00001000005f;
        const float CM1 = 1.00000500002e-05f;
#pragma unroll
        for (int s = 0; s < 16; s++) MB[s * 256 + tid] = 0.f;
        float E = 0.f;
#pragma unroll 2
        for (int m = m0; m < m0 + 64; m++) {
            const ulonglong2* k2 = (const ulonglong2*)(Ks + m * 8);
            ulonglong2 ka = k2[0], kb = k2[1];
            u64 d0 = ffma2(q2[0], ka.x, 0ULL);
            d0 = ffma2(q2[1], ka.y, d0);
            d0 = ffma2(q2[2], kb.x, d0);
            d0 = ffma2(q2[3], kb.y, d0);
            float e = __expf((hsum2(d0) - mx) * ESC);
            E += e;
            MB[stk[m] * 256 + tid] += e;
        }
        EB[tid] = E;
        __syncthreads();
        if (mh == 0) {
            float Et = EB[row] + EB[row + 64] + EB[row + 128] + EB[row + 192];
            float zi[16];
            float Sinv = 0.f;
#pragma unroll
            for (int s = 0; s < 16; s++) {
                float bsum = MB[s * 256 + row] + MB[s * 256 + row + 64]
                           + MB[s * 256 + row + 128] + MB[s * 256 + row + 192];
                float z = fmaf(-CM1, bsum, CC * Et);
                zi[s] = 1.f / z;
                Sinv += zi[s];
            }
#pragma unroll
            for (int s = 0; s < 16; s++)
                MB[s * 256 + row] = fmaf(-CM1, zi[s], CC * Sinv);   // coef_s
        }
        __syncthreads();
#pragma unroll 2
        for (int m = m0; m < m0 + 64; m++) {
            const ulonglong2* k2 = (const ulonglong2*)(Ks + m * 8);
            ulonglong2 ka = k2[0], kb = k2[1];
            u64 d0 = ffma2(q2[0], ka.x, 0ULL);
            d0 = ffma2(q2[1], ka.y, d0);
            d0 = ffma2(q2[2], kb.x, d0);
            d0 = ffma2(q2[3], kb.y, d0);
            float e = __expf((hsum2(d0) - mx) * ESC);
            float w = e * MB[stk[m] * 256 + row];
            u64 wp = f2pack(w, w);
            const ulonglong2* v2p = (const ulonglong2*)(Vs + m * 36);
#pragma unroll
            for (int g = 0; g < 8; g++) {
                ulonglong2 vv = v2p[g];
                o2[2 * g]     = ffma2(wp, vv.x, o2[2 * g]);
                o2[2 * g + 1] = ffma2(wp, vv.y, o2[2 * g + 1]);
            }
        }
        __syncthreads();   // all coef reads done; reuse MB for V merge
        if (mh != 0) {
#pragma unroll
            for (int j = 0; j < 16; j++) vm[row * 48 + (mh - 1) * 16 + j] = o2[j];
        }
        __syncthreads();
        if (mh == 0) {
            float vals[32];
#pragma unroll
            for (int g = 0; g < 16; g++) {
                o2[g] = fadd2(fadd2(o2[g], vm[row * 48 + g]),
                              fadd2(vm[row * 48 + 16 + g], vm[row * 48 + 32 + g]));
                float v0, v1;
                unpack2(o2[g], v0, v1);
                int c0 = 2 * g;
                float sc1, sh1, sc2, sh2;
                bn_coef(bnp, c0, 32, sc1, sh1);
                bn_coef(bnlb, c0, 32, sc2, sh2);
                float lb0 = gp[(lbbase + c0) * 256 + n];
                vals[c0] = fmaf(v0, sc1, sh1) + fmaf(lb0, sc2, sh2);
                bn_coef(bnp, c0 + 1, 32, sc1, sh1);
                bn_coef(bnlb, c0 + 1, 32, sc2, sh2);
                float lb1 = gp[(lbbase + c0 + 1) * 256 + n];
                vals[c0 + 1] = fmaf(v1, sc1, sh1) + fmaf(lb1, sc2, sh2);
            }
            float* fout = g_f + b * 16384 + n * 64 + choff;
#pragma unroll
            for (int q = 0; q < 8; q++)
                *(float4*)(fout + 4 * q) = *(float4*)(vals + 4 * q);
        }
    }
}

// ---------------- kernel 3a: MLP stage 1 ----------------
// h[n][o] = relu(bn1(w1 @ f[n][:]))   k-pair accumulation, zero packs.
// grid (16, 64): bx>>2 = o chunk (64), bx&3 = col chunk (64). block 256.
#define M1_SMEM_BYTES (64 * 68 * 4)

__global__ void mlp1_kernel(const float* __restrict__ w1, const float* __restrict__ bn1) {
    extern __shared__ float sm[];
    float* fs = sm;   // [col*68 + ch]

    int b = blockIdx.y, tid = threadIdx.x;
    int o0b = (blockIdx.x >> 2) * 64, n0 = (blockIdx.x & 3) * 64;

    for (int i = tid; i < 1024; i += 256) {
        int col = i >> 4, c4 = (i & 15) * 4;
        float4 v = *(const float4*)&g_f[b * 16384 + (n0 + col) * 64 + c4];
        *(float4*)(fs + col * 68 + c4) = v;
    }
    __syncthreads();

    int tx = tid & 15, ty = tid >> 4;
    int o0 = o0b + ty * 4;

    u64 acc[4][4];   // [o][col_j], f32x2 pairs along k
#pragma unroll
    for (int j = 0; j < 4; j++)
#pragma unroll
        for (int c = 0; c < 4; c++) acc[j][c] = 0ULL;

#pragma unroll 4
    for (int k4 = 0; k4 < 64; k4 += 4) {
        ulonglong2 w[4];
#pragma unroll
        for (int j = 0; j < 4; j++)
            w[j] = *(const ulonglong2*)&w1[(o0 + j) * 64 + k4];
        ulonglong2 f[4];
#pragma unroll
        for (int c = 0; c < 4; c++)
            f[c] = *(const ulonglong2*)(fs + (tx + 16 * c) * 68 + k4);
#pragma unroll
        for (int j = 0; j < 4; j++)
#pragma unroll
            for (int c = 0; c < 4; c++) {
                acc[j][c] = ffma2(w[j].x, f[c].x, acc[j][c]);
                acc[j][c] = ffma2(w[j].y, f[c].y, acc[j][c]);
            }
    }

    float sc[4], sh[4];
#pragma unroll
    for (int j = 0; j < 4; j++) bn_coef(bn1, o0 + j, 256, sc[j], sh[j]);

#pragma unroll
    for (int c = 0; c < 4; c++) {
        int n = n0 + tx + 16 * c;
        float4 r;
        r.x = fmaxf(fmaf(hsum2(acc[0][c]), sc[0], sh[0]), 0.f);
        r.y = fmaxf(fmaf(hsum2(acc[1][c]), sc[1], sh[1]), 0.f);
        r.z = fmaxf(fmaf(hsum2(acc[2][c]), sc[2], sh[2]), 0.f);
        r.w = fmaxf(fmaf(hsum2(acc[3][c]), sc[3], sh[3]), 0.f);
        *(float4*)&g_h[b * 65536 + n * 256 + o0] = r;
    }
}

// ---------------- kernel 3b: MLP stage 2 ----------------
// out[ch][n] = relu(bn2(w2 @ h[n][:]) + f[n][ch])   k-pair accumulation.
// grid (8, 64): bx = col chunk (32). block 256.
#define M2_SMEM_BYTES (32 * 260 * 4)

__global__ void mlp2_kernel(const float* __restrict__ w2, const float* __restrict__ bn2,
                            float* __restrict__ out) {
    extern __shared__ float sm[];
    float* hs = sm;   // [col*260 + k]

    int b = blockIdx.y, tid = threadIdx.x;
    int n0 = blockIdx.x * 32;

    for (int i = tid; i < 2048; i += 256) {
        int col = i >> 6, k4 = (i & 63) * 4;
        float4 v = *(const float4*)&g_h[b * 65536 + (n0 + col) * 256 + k4];
        *(float4*)(hs + col * 260 + k4) = v;
    }
    __syncthreads();

    int tx = tid & 7, ty = tid >> 3;
    int ch0 = ty * 2;

    u64 acc[2][4];
#pragma unroll
    for (int j = 0; j < 2; j++)
#pragma unroll
        for (int c = 0; c < 4; c++) acc[j][c] = 0ULL;

#pragma unroll 2
    for (int k4 = 0; k4 < 256; k4 += 4) {
        ulonglong2 w[2];
#pragma unroll
        for (int j = 0; j < 2; j++)
            w[j] = *(const ulonglong2*)&w2[(ch0 + j) * 256 + k4];
        ulonglong2 h[4];
#pragma unroll
        for (int c = 0; c < 4; c++)
            h[c] = *(const ulonglong2*)(hs + (tx + 8 * c) * 260 + k4);
#pragma unroll
        for (int j = 0; j < 2; j++)
#pragma unroll
            for (int c = 0; c < 4; c++) {
                acc[j][c] = ffma2(w[j].x, h[c].x, acc[j][c]);
                acc[j][c] = ffma2(w[j].y, h[c].y, acc[j][c]);
            }
    }

    float sc0, sh0, sc1, sh1;
    bn_coef(bn2, ch0, 64, sc0, sh0);
    bn_coef(bn2, ch0 + 1, 64, sc1, sh1);

#pragma unroll
    for (int c = 0; c < 4; c++) {
        int n = n0 + tx + 8 * c;
        const float* fres = &g_f[b * 16384 + n * 64 + ch0];
        float v0 = fmaf(hsum2(acc[0][c]), sc0, sh0) + fres[0];
        float v1 = fmaf(hsum2(acc[1][c]), sc1, sh1) + fres[1];
        out[b * 16384 + ch0 * 256 + n]       = fmaxf(v0, 0.f);
        out[b * 16384 + (ch0 + 1) * 256 + n] = fmaxf(v1, 0.f);
    }
}

// ---------------- launch ----------------
extern "C" void kernel_launch(void* const* d_in, const int* in_sizes, int n_in,
                              void* d_out, int out_size) {
    int base = (in_sizes[2] == 512) ? 2 : 3;

    const float* x          = (const float*)d_in[0];
    const int*   stroke     = (const int*)d_in[1];
    const float* ga_q_w     = (const float*)d_in[base + 0];
    const float* ga_k_w     = (const float*)d_in[base + 1];
    const float* ga_v_w     = (const float*)d_in[base + 2];
    const float* ga_v_b     = (const float*)d_in[base + 3];
    const float* ga_bn_p    = (const float*)d_in[base + 4];
    const float* ga_lb_w    = (const float*)d_in[base + 5];
    const float* ga_lb_bn_p = (const float*)d_in[base + 6];
    const float* sa_q_w     = (const float*)d_in[base + 7];
    const float* sa_k_w     = (const float*)d_in[base + 8];
    const float* sa_v_w     = (const float*)d_in[base + 9];
    const float* sa_v_b     = (const float*)d_in[base + 10];
    const float* sa_bn_p    = (const float*)d_in[base + 11];
    const float* sa_lb_w    = (const float*)d_in[base + 12];
    const float* sa_lb_bn_p = (const float*)d_in[base + 13];
    const float* mlp_w1     = (const float*)d_in[base + 14];
    const float* mlp_bn1_p  = (const float*)d_in[base + 15];
    const float* mlp_w2     = (const float*)d_in[base + 16];
    const float* mlp_bn2_p  = (const float*)d_in[base + 17];

    cudaFuncSetAttribute(attn_kernel, cudaFuncAttributeMaxDynamicSharedMemorySize, ATTN_SMEM_BYTES);
    cudaFuncSetAttribute(mlp1_kernel, cudaFuncAttributeMaxDynamicSharedMemorySize, M1_SMEM_BYTES);
    cudaFuncSetAttribute(mlp2_kernel, cudaFuncAttributeMaxDynamicSharedMemorySize, M2_SMEM_BYTES);

    proj_kernel<<<dim3(64, 16), 128>>>(x, ga_q_w, ga_k_w, ga_v_w, ga_lb_w,
                                       sa_q_w, sa_k_w, sa_v_w, sa_lb_w);
    attn_kernel<<<dim3(64, 8), 256, ATTN_SMEM_BYTES>>>(stroke, ga_v_b, sa_v_b,
                                                       ga_bn_p, ga_lb_bn_p,
                                                       sa_bn_p, sa_lb_bn_p);
    mlp1_kernel<<<dim3(16, 64), 256, M1_SMEM_BYTES>>>(mlp_w1, mlp_bn1_p);
    mlp2_kernel<<<dim3(8, 64), 256, M2_SMEM_BYTES>>>(mlp_w2, mlp_bn2_p, (float*)d_out);
}

// round 8
// speedup vs baseline: 1.1591x; 1.1591x over previous
#include <cuda_runtime.h>
#include <math.h>

#define BATCH 64
#define CH    64
#define NPT   256

typedef unsigned long long u64;

// ---------------- global scratch ----------------
// g_proj rows per batch: 0-7 ga_q, 8-15 ga_k, 16-47 ga_v(raw), 48-55 sa_q,
// 56-63 sa_k, 64-95 sa_v(raw), 96-127 ga_lb, 128-159 sa_lb
__device__ float g_proj[BATCH * 160 * NPT];
__device__ float g_f[BATCH * CH * NPT];    // [b][ch][n]
__device__ float g_h[BATCH * 256 * NPT];   // [b][o][n]

// ---------------- f32x2 helpers ----------------
__device__ __forceinline__ u64 f2pack(float a, float b) {
    u64 r;
    asm("mov.b64 %0, {%1, %2};" : "=l"(r) : "r"(__float_as_uint(a)), "r"(__float_as_uint(b)));
    return r;
}
__device__ __forceinline__ u64 ffma2(u64 a, u64 b, u64 c) {
    u64 d;
    asm("fma.rn.f32x2 %0, %1, %2, %3;" : "=l"(d) : "l"(a), "l"(b), "l"(c));
    return d;
}
__device__ __forceinline__ u64 fadd2(u64 a, u64 b) {
    u64 d;
    asm("add.rn.f32x2 %0, %1, %2;" : "=l"(d) : "l"(a), "l"(b));
    return d;
}
__device__ __forceinline__ void unpack2(u64 v, float& lo, float& hi) {
    unsigned int l, h;
    asm("mov.b64 {%0, %1}, %2;" : "=r"(l), "=r"(h) : "l"(v));
    lo = __uint_as_float(l);
    hi = __uint_as_float(h);
}
__device__ __forceinline__ float hsum2(u64 v) {
    float lo, hi;
    unpack2(v, lo, hi);
    return lo + hi;
}
__device__ __forceinline__ void bn_coef(const float* __restrict__ p, int ch, int cn,
                                        float& sc, float& sh) {
    float ga = __ldg(p + ch);
    float be = __ldg(p + cn + ch);
    float mu = __ldg(p + 2 * cn + ch);
    float va = __ldg(p + 3 * cn + ch);
    sc = ga * rsqrtf(va + 1e-5f);
    sh = fmaf(-mu, sc, be);
}

// ---------------- kernel 1: projections ----------------
// grid (64, 16): y>>1 = out group (20 rows), y&1 = n half. block 128.
__global__ void proj_kernel(const float* __restrict__ x,
                            const float* __restrict__ ga_q_w, const float* __restrict__ ga_k_w,
                            const float* __restrict__ ga_v_w, const float* __restrict__ ga_lb_w,
                            const float* __restrict__ sa_q_w, const float* __restrict__ sa_k_w,
                            const float* __restrict__ sa_v_w, const float* __restrict__ sa_lb_w) {
    __shared__ float ws[20 * 64];
    int b = blockIdx.x, tid = threadIdx.x;
    int og = blockIdx.y >> 1, nh = blockIdx.y & 1;
    int n = nh * 128 + tid;

    for (int i = tid; i < 1280; i += 128) {
        int r = og * 20 + (i >> 6), c = i & 63;
        float v;
        if      (r < 8)   v = __ldg(&ga_q_w[r * 64 + c]);
        else if (r < 16)  v = __ldg(&ga_k_w[(r - 8) * 64 + c]);
        else if (r < 48)  v = __ldg(&ga_v_w[(r - 16) * 64 + c]);
        else if (r < 56)  v = __ldg(&sa_q_w[(r - 48) * 64 + c]);
        else if (r < 64)  v = __ldg(&sa_k_w[(r - 56) * 64 + c]);
        else if (r < 96)  v = __ldg(&sa_v_w[(r - 64) * 64 + c]);
        else if (r < 128) v = __ldg(&ga_lb_w[(r - 96) * 64 + c]);
        else              v = __ldg(&sa_lb_w[(r - 128) * 64 + c]);
        ws[i] = v;
    }
    __syncthreads();

    u64 xr2[32];
#pragma unroll
    for (int c = 0; c < 32; c++) {
        float a = __ldg(&x[b * 16384 + (2 * c) * 256 + n]);
        float bb = __ldg(&x[b * 16384 + (2 * c + 1) * 256 + n]);
        xr2[c] = f2pack(a, bb);
    }

    float* outp = g_proj + (b * 160 + og * 20) * 256 + n;
#pragma unroll 2
    for (int o = 0; o < 20; o++) {
        const ulonglong2* w2 = (const ulonglong2*)(ws + o * 64);
        u64 a0 = 0ULL, a1 = 0ULL;
#pragma unroll
        for (int i = 0; i < 16; i++) {
            ulonglong2 wv = w2[i];
            a0 = ffma2(wv.x, xr2[2 * i], a0);
            a1 = ffma2(wv.y, xr2[2 * i + 1], a1);
        }
        outp[o * 256] = hsum2(fadd2(a0, a1));
    }
}

// ---------------- kernel 2: attention ----------------
// grid (64, 4): y>>1 = branch, y&1 = row half. block 256 = 128 rows x 2 m-halves.
#define KS_OFF  0
#define VS_OFF  2048
#define MB_OFF  11264     // 4352 floats: SA bins (16x256) / V-merge (128x17 u64)
#define MX_OFF  15616
#define EB_OFF  15872
#define STK_OFF 16128
#define ATTN_SMEM_BYTES (16384 * 4)

__global__ void attn_kernel(const int* __restrict__ stroke_idx,
                            const float* __restrict__ ga_v_b, const float* __restrict__ sa_v_b,
                            const float* __restrict__ ga_bn_p, const float* __restrict__ ga_lb_bn_p,
                            const float* __restrict__ sa_bn_p, const float* __restrict__ sa_lb_bn_p) {
    extern __shared__ float sm[];
    float* Ks   = sm + KS_OFF;     // [m*8 + j]
    float* Vs   = sm + VS_OFF;     // [m*36 + o]
    float* MB   = sm + MB_OFF;     // bins [s*256+tid] then V-merge
    float* MX   = sm + MX_OFF;
    float* EB   = sm + EB_OFF;
    int*   stk  = (int*)(sm + STK_OFF);

    int b = blockIdx.x, tid = threadIdx.x;
    int branch = blockIdx.y >> 1, rh = blockIdx.y & 1;
    int row = tid & 127, mh = tid >> 7;
    int n = rh * 128 + row;
    int m0 = mh * 128;

    int qbase  = branch ? 48 : 0;
    int kbase  = qbase + 8;
    int vbase  = branch ? 64 : 16;
    int lbbase = branch ? 128 : 96;
    const float* vb = branch ? sa_v_b : ga_v_b;
    const float* gp = g_proj + b * 160 * 256;

    for (int i = tid; i < 2048; i += 256) {
        int r = i >> 8, m = i & 255;
        Ks[m * 8 + r] = gp[(kbase + r) * 256 + m];
    }
    for (int i = tid; i < 8192; i += 256) {
        int r = i >> 8, m = i & 255;
        Vs[m * 36 + r] = gp[(vbase + r) * 256 + m] + __ldg(vb + r);
    }
    if (branch)
        for (int i = tid; i < 256; i += 256) stk[i] = stroke_idx[b * 256 + i];
    __syncthreads();

    u64 q2[4];
#pragma unroll
    for (int j = 0; j < 4; j++)
        q2[j] = f2pack(gp[(qbase + 2 * j) * 256 + n], gp[(qbase + 2 * j + 1) * 256 + n]);

    const float INV_GA = 0.35355339059327373f;   // 1/sqrt(8)
    const float ESC    = 3.5355339059327378f;    // 10/sqrt(8)

    float mxl = -1e30f;
#pragma unroll 4
    for (int m = m0; m < m0 + 128; m++) {
        const ulonglong2* k2 = (const ulonglong2*)(Ks + m * 8);
        ulonglong2 ka = k2[0], kb = k2[1];
        u64 d0 = ffma2(q2[0], ka.x, 0ULL);
        d0 = ffma2(q2[1], ka.y, d0);
        d0 = ffma2(q2[2], kb.x, d0);
        d0 = ffma2(q2[3], kb.y, d0);
        mxl = fmaxf(mxl, hsum2(d0));
    }
    MX[tid] = mxl;
    __syncthreads();
    float mx = fmaxf(MX[row], MX[row + 128]);

    u64 o2[16];
#pragma unroll
    for (int v = 0; v < 16; v++) o2[v] = 0ULL;
    u64* mb64 = (u64*)MB;

    if (branch == 0) {
        float sum = 0.f;
#pragma unroll 2
        for (int m = m0; m < m0 + 128; m++) {
            const ulonglong2* k2 = (const ulonglong2*)(Ks + m * 8);
            ulonglong2 ka = k2[0], kb = k2[1];
            u64 d0 = ffma2(q2[0], ka.x, 0ULL);
            d0 = ffma2(q2[1], ka.y, d0);
            d0 = ffma2(q2[2], kb.x, d0);
            d0 = ffma2(q2[3], kb.y, d0);
            float e = __expf((hsum2(d0) - mx) * INV_GA);
            sum += e;
            u64 ep = f2pack(e, e);
            const ulonglong2* v2p = (const ulonglong2*)(Vs + m * 36);
#pragma unroll
            for (int g = 0; g < 8; g++) {
                ulonglong2 vv = v2p[g];
                o2[2 * g]     = ffma2(ep, vv.x, o2[2 * g]);
                o2[2 * g + 1] = ffma2(ep, vv.y, o2[2 * g + 1]);
            }
        }
        EB[tid] = sum;
        __syncthreads();
        float sumt = EB[row] + EB[row + 128];
        if (mh == 1) {
#pragma unroll
            for (int j = 0; j < 16; j++) mb64[row * 17 + j] = o2[j];
        }
        __syncthreads();
        if (mh == 0) {
            float rcp = 1.f / sumt;
#pragma unroll
            for (int g = 0; g < 16; g++) {
                o2[g] = fadd2(o2[g], mb64[row * 17 + g]);
                float v0, v1;
                unpack2(o2[g], v0, v1);
                int c0 = 2 * g;
                float sc1, sh1, sc2, sh2;
                bn_coef(ga_bn_p, c0, 32, sc1, sh1);
                bn_coef(ga_lb_bn_p, c0, 32, sc2, sh2);
                float lb0 = gp[(lbbase + c0) * 256 + n];
                g_f[b * 16384 + c0 * 256 + n] = fmaf(v0 * rcp, sc1, sh1) + fmaf(lb0, sc2, sh2);
                bn_coef(ga_bn_p, c0 + 1, 32, sc1, sh1);
                bn_coef(ga_lb_bn_p, c0 + 1, 32, sc2, sh2);
                float lb1 = gp[(lbbase + c0 + 1) * 256 + n];
                g_f[b * 16384 + (c0 + 1) * 256 + n] = fmaf(v1 * rcp, sc1, sh1) + fmaf(lb1, sc2, sh2);
            }
        }
    } else {
        const float CC  = 1.00001000005f;
        const float CM1 = 1.00000500002e-05f;
#pragma unroll
        for (int s = 0; s < 16; s++) MB[s * 256 + tid] = 0.f;
        __syncthreads();
        float E = 0.f;
#pragma unroll 2
        for (int m = m0; m < m0 + 128; m++) {
            const ulonglong2* k2 = (const ulonglong2*)(Ks + m * 8);
            ulonglong2 ka = k2[0], kb = k2[1];
            u64 d0 = ffma2(q2[0], ka.x, 0ULL);
            d0 = ffma2(q2[1], ka.y, d0);
            d0 = ffma2(q2[2], kb.x, d0);
            d0 = ffma2(q2[3], kb.y, d0);
            float e = __expf((hsum2(d0) - mx) * ESC);
            E += e;
            MB[stk[m] * 256 + tid] += e;
        }
        EB[tid] = E;
        __syncthreads();
        if (mh == 0) {
            float Et = EB[row] + EB[row + 128];
            float zi[16];
            float Sinv = 0.f;
#pragma unroll
            for (int s = 0; s < 16; s++) {
                float bsum = MB[s * 256 + row] + MB[s * 256 + row + 128];
                float z = fmaf(-CM1, bsum, CC * Et);
                zi[s] = 1.f / z;
                Sinv += zi[s];
            }
#pragma unroll
            for (int s = 0; s < 16; s++)
                MB[s * 256 + row] = fmaf(-CM1, zi[s], CC * Sinv);   // coef_s
        }
        __syncthreads();
#pragma unroll 2
        for (int m = m0; m < m0 + 128; m++) {
            const ulonglong2* k2 = (const ulonglong2*)(Ks + m * 8);
            ulonglong2 ka = k2[0], kb = k2[1];
            u64 d0 = ffma2(q2[0], ka.x, 0ULL);
            d0 = ffma2(q2[1], ka.y, d0);
            d0 = ffma2(q2[2], kb.x, d0);
            d0 = ffma2(q2[3], kb.y, d0);
            float e = __expf((hsum2(d0) - mx) * ESC);
            float w = e * MB[stk[m] * 256 + row];
            u64 wp = f2pack(w, w);
            const ulonglong2* v2p = (const ulonglong2*)(Vs + m * 36);
#pragma unroll
            for (int g = 0; g < 8; g++) {
                ulonglong2 vv = v2p[g];
                o2[2 * g]     = ffma2(wp, vv.x, o2[2 * g]);
                o2[2 * g + 1] = ffma2(wp, vv.y, o2[2 * g + 1]);
            }
        }
        __syncthreads();   // bins done; reuse MB for V merge
        if (mh == 1) {
#pragma unroll
            for (int j = 0; j < 16; j++) mb64[row * 17 + j] = o2[j];
        }
        __syncthreads();
        if (mh == 0) {
#pragma unroll
            for (int g = 0; g < 16; g++) {
                o2[g] = fadd2(o2[g], mb64[row * 17 + g]);
                float v0, v1;
                unpack2(o2[g], v0, v1);
                int c0 = 2 * g;
                float sc1, sh1, sc2, sh2;
                bn_coef(sa_bn_p, c0, 32, sc1, sh1);
                bn_coef(sa_lb_bn_p, c0, 32, sc2, sh2);
                float lb0 = gp[(lbbase + c0) * 256 + n];
                g_f[b * 16384 + (32 + c0) * 256 + n] = fmaf(v0, sc1, sh1) + fmaf(lb0, sc2, sh2);
                bn_coef(sa_bn_p, c0 + 1, 32, sc1, sh1);
                bn_coef(sa_lb_bn_p, c0 + 1, 32, sc2, sh2);
                float lb1 = gp[(lbbase + c0 + 1) * 256 + n];
                g_f[b * 16384 + (32 + c0 + 1) * 256 + n] = fmaf(v1, sc1, sh1) + fmaf(lb1, sc2, sh2);
            }
        }
    }
}

// ---------------- kernel 3a: MLP stage 1 (h = relu(bn1(w1@f))) ----------------
// grid (8, 64): bx>>1 = ch chunk (64 of 256), bx&1 = col chunk (128). block 256.
#define M1_W_OFF 0
#define M1_F_OFF 4352                       // w1s = 64*68
#define M1_SMEM_BYTES ((4352 + 8448) * 4)   // + fs = 64*132

__global__ void mlp1_kernel(const float* __restrict__ w1, const float* __restrict__ bn1) {
    extern __shared__ float sm[];
    float* w1s = sm + M1_W_OFF;   // [k*68 + o]
    float* fs  = sm + M1_F_OFF;   // [k*132 + col]

    int b = blockIdx.y, tid = threadIdx.x;
    int cc = blockIdx.x >> 1, nc = blockIdx.x & 1;
    int tx = tid & 31, ty = tid >> 5;

    for (int i = tid; i < 4096; i += 256) {
        int o = i >> 6, k = i & 63;
        w1s[k * 68 + o] = __ldg(&w1[(cc * 64 + o) * 64 + k]);
    }
    for (int i = tid; i < 8192; i += 256) {
        int k = i >> 7, col = i & 127;
        fs[k * 132 + col] = g_f[b * 16384 + k * 256 + nc * 128 + col];
    }
    __syncthreads();

    u64 acc[4][4];
#pragma unroll
    for (int p = 0; p < 4; p++)
#pragma unroll
        for (int c = 0; c < 4; c++) acc[p][c] = 0ULL;

#pragma unroll 4
    for (int k = 0; k < 64; k++) {
        const ulonglong2* wv2 = (const ulonglong2*)(w1s + k * 68 + ty * 8);
        ulonglong2 wa = wv2[0], wb = wv2[1];
        float4 hv = *(const float4*)(fs + k * 132 + tx * 4);
        u64 h0 = f2pack(hv.x, hv.x), h1 = f2pack(hv.y, hv.y);
        u64 h2 = f2pack(hv.z, hv.z), h3 = f2pack(hv.w, hv.w);
        acc[0][0] = ffma2(wa.x, h0, acc[0][0]);
        acc[0][1] = ffma2(wa.x, h1, acc[0][1]);
        acc[0][2] = ffma2(wa.x, h2, acc[0][2]);
        acc[0][3] = ffma2(wa.x, h3, acc[0][3]);
        acc[1][0] = ffma2(wa.y, h0, acc[1][0]);
        acc[1][1] = ffma2(wa.y, h1, acc[1][1]);
        acc[1][2] = ffma2(wa.y, h2, acc[1][2]);
        acc[1][3] = ffma2(wa.y, h3, acc[1][3]);
        acc[2][0] = ffma2(wb.x, h0, acc[2][0]);
        acc[2][1] = ffma2(wb.x, h1, acc[2][1]);
        acc[2][2] = ffma2(wb.x, h2, acc[2][2]);
        acc[2][3] = ffma2(wb.x, h3, acc[2][3]);
        acc[3][0] = ffma2(wb.y, h0, acc[3][0]);
        acc[3][1] = ffma2(wb.y, h1, acc[3][1]);
        acc[3][2] = ffma2(wb.y, h2, acc[3][2]);
        acc[3][3] = ffma2(wb.y, h3, acc[3][3]);
    }

    int n0 = nc * 128 + tx * 4;
#pragma unroll
    for (int p = 0; p < 4; p++) {
        int ch0 = cc * 64 + ty * 8 + 2 * p;
        float sc0, sh0, sc1s, sh1s;
        bn_coef(bn1, ch0, 256, sc0, sh0);
        bn_coef(bn1, ch0 + 1, 256, sc1s, sh1s);
        float4 r0, r1;
        float a, bb;
        unpack2(acc[p][0], a, bb); r0.x = fmaxf(fmaf(a, sc0, sh0), 0.f); r1.x = fmaxf(fmaf(bb, sc1s, sh1s), 0.f);
        unpack2(acc[p][1], a, bb); r0.y = fmaxf(fmaf(a, sc0, sh0), 0.f); r1.y = fmaxf(fmaf(bb, sc1s, sh1s), 0.f);
        unpack2(acc[p][2], a, bb); r0.z = fmaxf(fmaf(a, sc0, sh0), 0.f); r1.z = fmaxf(fmaf(bb, sc1s, sh1s), 0.f);
        unpack2(acc[p][3], a, bb); r0.w = fmaxf(fmaf(a, sc0, sh0), 0.f); r1.w = fmaxf(fmaf(bb, sc1s, sh1s), 0.f);
        *(float4*)&g_h[b * 65536 + ch0 * 256 + n0]       = r0;
        *(float4*)&g_h[b * 65536 + (ch0 + 1) * 256 + n0] = r1;
    }
}

// ---------------- kernel 3b: MLP stage 2, single pass + intra-block k-split ----------------
// grid (4, 64): bx = col chunk (64). block 512 = 2 k-halves x 256.
// h tile resident in smem; w2 streamed via warp-broadcast LDG.128.
#define M2_SMEM_BYTES (256 * 68 * 4)

__global__ void mlp2_kernel(const float* __restrict__ w2, const float* __restrict__ bn2,
                            float* __restrict__ out) {
    extern __shared__ float sm[];
    float* hs = sm;   // [k*68 + col], k=0..255, col=0..63

    int b = blockIdx.y, tid = threadIdx.x;
    int n0b = blockIdx.x * 64;
    int kh = tid >> 8, t = tid & 255;

    // load full h tile: 256 k x 64 cols, vectorized (512 threads)
    for (int i = tid; i < 4096; i += 512) {
        int k = i >> 4, col0 = (i & 15) * 4;
        float4 v = *(const float4*)&g_h[b * 65536 + k * 256 + n0b + col0];
        *(float4*)(hs + k * 68 + col0) = v;
    }
    __syncthreads();

    int tx = t & 15, ty = t >> 4;
    int c0 = ty * 4, col0 = tx * 4;
    int kbeg = kh * 128, kend = kbeg + 128;

    u64 acc[4][2];
#pragma unroll
    for (int j = 0; j < 4; j++) { acc[j][0] = 0ULL; acc[j][1] = 0ULL; }

#pragma unroll 2
    for (int k4 = kbeg; k4 < kend; k4 += 4) {
        float4 w[4];
#pragma unroll
        for (int j = 0; j < 4; j++)
            w[j] = __ldg((const float4*)&w2[(c0 + j) * 256 + k4]);
#pragma unroll
        for (int kk = 0; kk < 4; kk++) {
            ulonglong2 hv = *(const ulonglong2*)(hs + (k4 + kk) * 68 + col0);
#pragma unroll
            for (int j = 0; j < 4; j++) {
                float wv = (kk == 0) ? w[j].x : (kk == 1) ? w[j].y : (kk == 2) ? w[j].z : w[j].w;
                u64 wp = f2pack(wv, wv);
                acc[j][0] = ffma2(wp, hv.x, acc[j][0]);
                acc[j][1] = ffma2(wp, hv.y, acc[j][1]);
            }
        }
    }

    // merge the two k-halves through smem (hs no longer needed)
    __syncthreads();
    u64* red = (u64*)sm;   // 256 threads x 8 u64 = 16 KB
    if (kh == 1) {
#pragma unroll
        for (int j = 0; j < 4; j++) {
            red[t * 8 + 2 * j]     = acc[j][0];
            red[t * 8 + 2 * j + 1] = acc[j][1];
        }
    }
    __syncthreads();
    if (kh == 0) {
        int n0 = n0b + col0;
#pragma unroll
        for (int j = 0; j < 4; j++) {
            acc[j][0] = fadd2(acc[j][0], red[t * 8 + 2 * j]);
            acc[j][1] = fadd2(acc[j][1], red[t * 8 + 2 * j + 1]);
            int c = c0 + j;
            float sc, sh;
            bn_coef(bn2, c, 64, sc, sh);
            float4 f0 = *(const float4*)&g_f[b * 16384 + c * 256 + n0];
            float v0, v1, v2, v3;
            unpack2(acc[j][0], v0, v1);
            unpack2(acc[j][1], v2, v3);
            float4 r;
            r.x = fmaxf(fmaf(v0, sc, sh) + f0.x, 0.f);
            r.y = fmaxf(fmaf(v1, sc, sh) + f0.y, 0.f);
            r.z = fmaxf(fmaf(v2, sc, sh) + f0.z, 0.f);
            r.w = fmaxf(fmaf(v3, sc, sh) + f0.w, 0.f);
            *(float4*)&out[b * 16384 + c * 256 + n0] = r;
        }
    }
}

// ---------------- launch ----------------
extern "C" void kernel_launch(void* const* d_in, const int* in_sizes, int n_in,
                              void* d_out, int out_size) {
    int base = (in_sizes[2] == 512) ? 2 : 3;

    const float* x          = (const float*)d_in[0];
    const int*   stroke     = (const int*)d_in[1];
    const float* ga_q_w     = (const float*)d_in[base + 0];
    const float* ga_k_w     = (const float*)d_in[base + 1];
    const float* ga_v_w     = (const float*)d_in[base + 2];
    const float* ga_v_b     = (const float*)d_in[base + 3];
    const float* ga_bn_p    = (const float*)d_in[base + 4];
    const float* ga_lb_w    = (const float*)d_in[base + 5];
    const float* ga_lb_bn_p = (const float*)d_in[base + 6];
    const float* sa_q_w     = (const float*)d_in[base + 7];
    const float* sa_k_w     = (const float*)d_in[base + 8];
    const float* sa_v_w     = (const float*)d_in[base + 9];
    const float* sa_v_b     = (const float*)d_in[base + 10];
    const float* sa_bn_p    = (const float*)d_in[base + 11];
    const float* sa_lb_w    = (const float*)d_in[base + 12];
    const float* sa_lb_bn_p = (const float*)d_in[base + 13];
    const float* mlp_w1     = (const float*)d_in[base + 14];
    const float* mlp_bn1_p  = (const float*)d_in[base + 15];
    const float* mlp_w2     = (const float*)d_in[base + 16];
    const float* mlp_bn2_p  = (const float*)d_in[base + 17];

    cudaFuncSetAttribute(attn_kernel, cudaFuncAttributeMaxDynamicSharedMemorySize, ATTN_SMEM_BYTES);
    cudaFuncSetAttribute(mlp1_kernel, cudaFuncAttributeMaxDynamicSharedMemorySize, M1_SMEM_BYTES);
    cudaFuncSetAttribute(mlp2_kernel, cudaFuncAttributeMaxDynamicSharedMemorySize, M2_SMEM_BYTES);

    proj_kernel<<<dim3(64, 16), 128>>>(x, ga_q_w, ga_k_w, ga_v_w, ga_lb_w,
                                       sa_q_w, sa_k_w, sa_v_w, sa_lb_w);
    attn_kernel<<<dim3(64, 4), 256, ATTN_SMEM_BYTES>>>(stroke, ga_v_b, sa_v_b,
                                                       ga_bn_p, ga_lb_bn_p,
                                                       sa_bn_p, sa_lb_bn_p);
    mlp1_kernel<<<dim3(8, 64), 256, M1_SMEM_BYTES>>>(mlp_w1, mlp_bn1_p);
    mlp2_kernel<<<dim3(4, 64), 512, M2_SMEM_BYTES>>>(mlp_w2, mlp_bn2_p, (float*)d_out);
}